// round 1
// baseline (speedup 1.0000x reference)
#include <cuda_runtime.h>
#include <math.h>

#define T_DATA   50000
#define E_NO     1000
#define I_NO     200
#define SUB_NO   20
#define H_NO     16
#define T_NO     200
#define COS_NO   20

#define S_PITCH  50432            // >= 199 + 50000 + conv read overhang (455-199), 16B aligned
#define CONV_TT  256              // time tile for conv kernel
#define PI_F     3.14159265358979323846f
#define HALF_PI_F 1.57079632679489662f

// ---------------- device scratch (no allocations allowed) ----------------
__device__ float g_S[2 * SUB_NO * S_PITCH];          // [40][S_PITCH], ch-major, left pad 199 zeros
__device__ float g_kern[SUB_NO * H_NO * 2 * T_NO];   // unflipped einsum kernel [o][c][d]
__device__ float g_partial[SUB_NO * T_DATA];         // per-subunit root partials

// ---------------- zero g_S ----------------
__global__ void zero_S_kernel() {
    int i = blockIdx.x * blockDim.x + threadIdx.x;
    float4* p = reinterpret_cast<float4*>(g_S);
    if (i < (2 * SUB_NO * S_PITCH) / 4) p[i] = make_float4(0.f, 0.f, 0.f, 0.f);
}

// ---------------- basis * W_conv -> g_kern (+ flipped copy to output) ----------------
__global__ void kern_basis_kernel(const float* __restrict__ W_conv,
                                  float* __restrict__ out_kern /* may be null */) {
    int n = blockIdx.x * blockDim.x + threadIdx.x;
    if (n >= SUB_NO * H_NO * 2 * T_NO) return;
    int o = n / (2 * T_NO);
    int r = n % (2 * T_NO);
    int c = r / T_NO;
    int t = r % T_NO;
    float raw = 5.0f * logf((float)t + 1.0f);
    float acc = 0.f;
#pragma unroll
    for (int b = 0; b < COS_NO; ++b) {
        float phi = HALF_PI_F * (float)b;
        float dlt = raw - phi;
        if (raw >= phi - PI_F && raw <= phi + PI_F) {
            float bas = 0.5f * cosf(dlt) + 0.5f;
            acc += W_conv[(o * 2 + c) * COS_NO + b] * bas;
        }
    }
    g_kern[n] = acc;                                         // unflipped (conv form)
    if (out_kern) out_kern[o * 2 * T_NO + c * T_NO + (T_NO - 1 - t)] = acc;  // flipped (returned)
}

// ---------------- GEMM1: Sg = S @ C^T, interleaved into g_S ----------------
// block: 128 threads, 128 t rows. thread: tg=tid&31 (t = t0+tg+32*j), sg=tid>>5 (subs sg*5..+4)
__global__ __launch_bounds__(128) void gemm1_kernel(const float* __restrict__ Se,
                                                    const float* __restrict__ Si,
                                                    const float* __restrict__ Ce,
                                                    const float* __restrict__ Ci) {
    __shared__ __align__(16) float sA[128 * 36];
    __shared__ __align__(16) float sB[20 * 36];
    const int t0 = blockIdx.x * 128;
    const int tid = threadIdx.x;
    const int tg = tid & 31;
    const int sg = tid >> 5;

    for (int phase = 0; phase < 2; ++phase) {
        const float* A = phase ? Si : Se;
        const float* B = phase ? Ci : Ce;
        const int K = phase ? I_NO : E_NO;
        float acc[4][5];
#pragma unroll
        for (int j = 0; j < 4; ++j)
#pragma unroll
            for (int u = 0; u < 5; ++u) acc[j][u] = 0.f;

        const int nkt = (K + 31) >> 5;
        for (int kt = 0; kt < nkt; ++kt) {
            const int k0 = kt << 5;
            __syncthreads();
            // load A tile [128][32] coalesced
            for (int i = tid; i < 128 * 32; i += 128) {
                int r = i >> 5, kk = i & 31;
                int t = t0 + r, k = k0 + kk;
                sA[r * 36 + kk] = (t < T_DATA && k < K) ? A[(long)t * K + k] : 0.f;
            }
            // load B tile [20][32]
            for (int i = tid; i < 20 * 32; i += 128) {
                int su = i >> 5, kk = i & 31;
                int k = k0 + kk;
                sB[su * 36 + kk] = (k < K) ? B[su * K + k] : 0.f;
            }
            __syncthreads();
#pragma unroll
            for (int k4 = 0; k4 < 8; ++k4) {
                float4 a[4], b[5];
#pragma unroll
                for (int j = 0; j < 4; ++j)
                    a[j] = *reinterpret_cast<const float4*>(&sA[(tg + 32 * j) * 36 + k4 * 4]);
#pragma unroll
                for (int u = 0; u < 5; ++u)
                    b[u] = *reinterpret_cast<const float4*>(&sB[(sg * 5 + u) * 36 + k4 * 4]);
#pragma unroll
                for (int j = 0; j < 4; ++j)
#pragma unroll
                    for (int u = 0; u < 5; ++u) {
                        acc[j][u] += a[j].x * b[u].x;
                        acc[j][u] += a[j].y * b[u].y;
                        acc[j][u] += a[j].z * b[u].z;
                        acc[j][u] += a[j].w * b[u].w;
                    }
            }
        }
#pragma unroll
        for (int j = 0; j < 4; ++j) {
            int t = t0 + tg + 32 * j;
            if (t < T_DATA) {
#pragma unroll
                for (int u = 0; u < 5; ++u) {
                    int ch = 2 * (sg * 5 + u) + phase;   // interleave [e0,i0,e1,i1,...]
                    g_S[(long)ch * S_PITCH + (T_NO - 1) + t] = acc[j][u];
                }
            }
        }
        __syncthreads();
    }
}

// ---------------- fused conv (causal, 200 taps, 2 in-ch) + leaky + 2x16 MLP + root partial ----
// grid: (ceil(T/256), SUB_NO), block 128
__global__ __launch_bounds__(128) void conv_mlp_kernel(const float* __restrict__ ff_w,
                                                       const float* __restrict__ ff_b,
                                                       const float* __restrict__ ff2_w,
                                                       const float* __restrict__ ff2_b,
                                                       const float* __restrict__ root_w) {
    __shared__ __align__(16) float sm[7312];     // [0,6400)=sK(conv)/sX+W(mlp), [6400,7312)=sS
    float* sK = sm;                               // [2][16][200]
    float* sS = sm + 6400;                        // [2][456]
    const int s = blockIdx.y;
    const int t0 = blockIdx.x * CONV_TT;
    const int tid = threadIdx.x;

    // load kernel taps: g_kern subunit block is [h][c][d]; store as [c][h][d]
    const float* gk = g_kern + (long)s * H_NO * 2 * T_NO;
    for (int i = tid; i < H_NO * 2 * T_NO; i += 128) {
        int h = i / (2 * T_NO);
        int r = i % (2 * T_NO);
        int c = r / T_NO;
        int d = r % T_NO;
        sK[c * (H_NO * T_NO) + h * T_NO + d] = gk[i];
    }
    // load S window: x covers global t in [t0-199, t0+256)
    for (int i = tid; i < 2 * 456; i += 128) {
        int c = i / 456, x = i % 456;
        sS[i] = g_S[(long)(2 * s + c) * S_PITCH + t0 + x];
    }
    __syncthreads();

    const int hg = tid >> 5;       // 4 h-groups (x4 h each)
    const int tg = tid & 31;       // 32 t-groups (x8 t each)
    const int tb = tg * 8;

    float acc[4][8];
#pragma unroll
    for (int h = 0; h < 4; ++h)
#pragma unroll
        for (int j = 0; j < 8; ++j) acc[h][j] = 0.f;

    for (int c = 0; c < 2; ++c) {
        const float* kc = sK + c * (H_NO * T_NO) + (hg * 4) * T_NO;
        const float* sc = sS + c * 456;
#pragma unroll 2
        for (int d = 0; d < T_NO; d += 4) {
            float kk[4][4];
#pragma unroll
            for (int h = 0; h < 4; ++h) {
                float4 kv = *reinterpret_cast<const float4*>(kc + h * T_NO + d);
                kk[h][0] = kv.x; kk[h][1] = kv.y; kk[h][2] = kv.z; kk[h][3] = kv.w;
            }
            const int x0 = tb + 196 - d;           // sS index of S[t0+tb - d - 3]
            float w[12];
            float4 wa = *reinterpret_cast<const float4*>(sc + x0);
            float4 wb = *reinterpret_cast<const float4*>(sc + x0 + 4);
            float4 wc = *reinterpret_cast<const float4*>(sc + x0 + 8);
            w[0] = wa.x; w[1] = wa.y; w[2] = wa.z; w[3] = wa.w;
            w[4] = wb.x; w[5] = wb.y; w[6] = wb.z; w[7] = wb.w;
            w[8] = wc.x; w[9] = wc.y; w[10] = wc.z; w[11] = wc.w;
            // acc[h][j] += k[h][d+m] * S[t0+tb+j-(d+m)];  S[..] = w[j+3-m]
#pragma unroll
            for (int h = 0; h < 4; ++h)
#pragma unroll
                for (int m = 0; m < 4; ++m)
#pragma unroll
                    for (int j = 0; j < 8; ++j)
                        acc[h][j] += kk[h][m] * w[j + 3 - m];
        }
    }
    __syncthreads();   // done reading sK/sS region that sX/weights will overwrite

    // leaky relu + transpose into sX[h][t] (stride 264)
    float* sX  = sm;            // [16][264] = 4224
    float* sW1 = sm + 4224;     // 256
    float* sW2 = sm + 4480;     // 256
    float* sb1 = sm + 4736;     // 16
    float* sb2 = sm + 4752;     // 16
    float* sr  = sm + 4768;     // 16
#pragma unroll
    for (int h = 0; h < 4; ++h) {
        float4 v0, v1;
        v0.x = acc[h][0] > 0.f ? acc[h][0] : 0.01f * acc[h][0];
        v0.y = acc[h][1] > 0.f ? acc[h][1] : 0.01f * acc[h][1];
        v0.z = acc[h][2] > 0.f ? acc[h][2] : 0.01f * acc[h][2];
        v0.w = acc[h][3] > 0.f ? acc[h][3] : 0.01f * acc[h][3];
        v1.x = acc[h][4] > 0.f ? acc[h][4] : 0.01f * acc[h][4];
        v1.y = acc[h][5] > 0.f ? acc[h][5] : 0.01f * acc[h][5];
        v1.z = acc[h][6] > 0.f ? acc[h][6] : 0.01f * acc[h][6];
        v1.w = acc[h][7] > 0.f ? acc[h][7] : 0.01f * acc[h][7];
        int hglob = hg * 4 + h;
        *reinterpret_cast<float4*>(&sX[hglob * 264 + tb])     = v0;
        *reinterpret_cast<float4*>(&sX[hglob * 264 + tb + 4]) = v1;
    }
    for (int i = tid; i < 256; i += 128) {
        sW1[i] = ff_w[s * 256 + i];
        sW2[i] = ff2_w[s * 256 + i];
    }
    if (tid < 16) {
        sb1[tid] = ff_b[s * 16 + tid];
        sb2[tid] = ff2_b[s * 16 + tid];
        sr[tid]  = root_w[s * 16 + tid];
    }
    __syncthreads();

#pragma unroll
    for (int tt = 0; tt < 2; ++tt) {
        int tl = tid + tt * 128;
        int t = t0 + tl;
        if (t < T_DATA) {
            float x[16];
#pragma unroll
            for (int i = 0; i < 16; ++i) x[i] = sX[i * 264 + tl];
            float h1[16];
#pragma unroll
            for (int o = 0; o < 16; ++o) {
                float4 w0 = *reinterpret_cast<const float4*>(&sW1[o * 16]);
                float4 w1 = *reinterpret_cast<const float4*>(&sW1[o * 16 + 4]);
                float4 w2 = *reinterpret_cast<const float4*>(&sW1[o * 16 + 8]);
                float4 w3 = *reinterpret_cast<const float4*>(&sW1[o * 16 + 12]);
                float a = sb1[o];
                a += w0.x * x[0] + w0.y * x[1] + w0.z * x[2] + w0.w * x[3];
                a += w1.x * x[4] + w1.y * x[5] + w1.z * x[6] + w1.w * x[7];
                a += w2.x * x[8] + w2.y * x[9] + w2.z * x[10] + w2.w * x[11];
                a += w3.x * x[12] + w3.y * x[13] + w3.z * x[14] + w3.w * x[15];
                h1[o] = a > 0.f ? a : 0.01f * a;
            }
            float part = 0.f;
#pragma unroll
            for (int o = 0; o < 16; ++o) {
                float4 w0 = *reinterpret_cast<const float4*>(&sW2[o * 16]);
                float4 w1 = *reinterpret_cast<const float4*>(&sW2[o * 16 + 4]);
                float4 w2 = *reinterpret_cast<const float4*>(&sW2[o * 16 + 8]);
                float4 w3 = *reinterpret_cast<const float4*>(&sW2[o * 16 + 12]);
                float a = sb2[o];
                a += w0.x * h1[0] + w0.y * h1[1] + w0.z * h1[2] + w0.w * h1[3];
                a += w1.x * h1[4] + w1.y * h1[5] + w1.z * h1[6] + w1.w * h1[7];
                a += w2.x * h1[8] + w2.y * h1[9] + w2.z * h1[10] + w2.w * h1[11];
                a += w3.x * h1[12] + w3.y * h1[13] + w3.z * h1[14] + w3.w * h1[15];
                float h2 = a > 0.f ? a : 0.01f * a;
                part += sr[o] * h2;
            }
            g_partial[(long)s * T_DATA + t] = part;
        }
    }
}

// ---------------- reduce over subunits + bias ----------------
__global__ void reduce_kernel(const float* __restrict__ root_b,
                              const float* __restrict__ V_o,
                              float* __restrict__ out) {
    int t = blockIdx.x * blockDim.x + threadIdx.x;
    if (t >= T_DATA) return;
    float acc = root_b[0] + V_o[0];
#pragma unroll
    for (int s = 0; s < SUB_NO; ++s) acc += g_partial[(long)s * T_DATA + t];
    out[t] = acc;
}

// ---------------- launch ----------------
extern "C" void kernel_launch(void* const* d_in, const int* in_sizes, int n_in,
                              void* d_out, int out_size) {
    const float* S_e    = (const float*)d_in[0];
    const float* S_i    = (const float*)d_in[1];
    const float* C_e    = (const float*)d_in[2];
    const float* C_i    = (const float*)d_in[3];
    const float* W_conv = (const float*)d_in[4];
    const float* ff_w   = (const float*)d_in[5];
    const float* ff_b   = (const float*)d_in[6];
    const float* ff2_w  = (const float*)d_in[7];
    const float* ff2_b  = (const float*)d_in[8];
    const float* root_w = (const float*)d_in[9];
    const float* root_b = (const float*)d_in[10];
    const float* V_o    = (const float*)d_in[11];
    float* out = (float*)d_out;

    // zero g_S (left pad + read overhang)
    zero_S_kernel<<<(2 * SUB_NO * S_PITCH / 4 + 255) / 256, 256>>>();

    // temporal kernels; flipped copy goes to output if it fits
    float* kern_out = (out_size >= T_DATA + SUB_NO * H_NO * 2 * T_NO) ? (out + T_DATA) : nullptr;
    kern_basis_kernel<<<(SUB_NO * H_NO * 2 * T_NO + 255) / 256, 256>>>(W_conv, kern_out);

    // synapse grouping GEMMs -> interleaved channel-major g_S
    gemm1_kernel<<<(T_DATA + 127) / 128, 128>>>(S_e, S_i, C_e, C_i);

    // fused conv + MLP + root partials
    dim3 grid((T_DATA + CONV_TT - 1) / CONV_TT, SUB_NO);
    conv_mlp_kernel<<<grid, 128>>>(ff_w, ff_b, ff2_w, ff2_b, root_w);

    // final reduction -> V
    reduce_kernel<<<(T_DATA + 255) / 256, 256>>>(root_b, V_o, out);
}

// round 3
// speedup vs baseline: 1.2621x; 1.2621x over previous
#include <cuda_runtime.h>
#include <math.h>

#define T_DATA   50000
#define E_NO     1000
#define I_NO     200
#define SUB_NO   20
#define H_NO     16
#define T_NO     200
#define COS_NO   20

#define S_PITCH  50432            // 199 pad + 50000 + tail overhang, float4 aligned
#define CONV_TT  512              // time tile for conv kernel
#define PI_F     3.14159265358979323846f
#define HALF_PI_F 1.57079632679489662f

// ---------------- device scratch (no allocations allowed) ----------------
__device__ float g_S[2 * SUB_NO * S_PITCH];          // [40][S_PITCH], ch-major, left pad 199 zeros
__device__ float g_kern2[SUB_NO * 2 * H_NO * T_NO];  // transposed [s][c][h][d] for conv prologue
__device__ float g_partial[SUB_NO * T_DATA];         // per-subunit root partials

// ---------------- zero only pad + tail of g_S ----------------
// per channel: x in [0,199) and [199+T_DATA, S_PITCH)  -> 199 + 233 = 432 elems
__global__ void zero_pad_kernel() {
    int i = blockIdx.x * blockDim.x + threadIdx.x;
    const int per_ch = 199 + (S_PITCH - (199 + T_DATA));   // 432
    if (i >= 2 * SUB_NO * per_ch) return;
    int ch = i / per_ch;
    int r = i % per_ch;
    int x = (r < 199) ? r : (199 + T_DATA) + (r - 199);
    g_S[(long)ch * S_PITCH + x] = 0.f;
}

// ---------------- basis * W_conv -> g_kern2 (+ flipped copy to output) ----------------
__global__ void kern_basis_kernel(const float* __restrict__ W_conv,
                                  float* __restrict__ out_kern /* may be null */) {
    int n = blockIdx.x * blockDim.x + threadIdx.x;
    if (n >= SUB_NO * H_NO * 2 * T_NO) return;
    int o = n / (2 * T_NO);          // o = s*16 + h
    int r = n % (2 * T_NO);
    int c = r / T_NO;
    int t = r % T_NO;
    int s = o / H_NO;
    int h = o % H_NO;
    float raw = 5.0f * logf((float)t + 1.0f);
    float acc = 0.f;
#pragma unroll
    for (int b = 0; b < COS_NO; ++b) {
        float phi = HALF_PI_F * (float)b;
        float dlt = raw - phi;
        if (raw >= phi - PI_F && raw <= phi + PI_F) {
            float bas = 0.5f * cosf(dlt) + 0.5f;
            acc += W_conv[(o * 2 + c) * COS_NO + b] * bas;
        }
    }
    g_kern2[((s * 2 + c) * H_NO + h) * T_NO + t] = acc;                   // [s][c][h][d]
    if (out_kern) out_kern[o * 2 * T_NO + c * T_NO + (T_NO - 1 - t)] = acc;  // flipped (returned)
}

// ---------------- GEMM1: Sg = S @ C^T, interleaved into g_S ----------------
// one t-row per thread; B in smem read via warp-broadcast LDS.128; A streamed LDG.128.
__global__ __launch_bounds__(256) void gemm1_kernel(const float* __restrict__ Se,
                                                    const float* __restrict__ Si,
                                                    const float* __restrict__ Ce,
                                                    const float* __restrict__ Ci) {
    __shared__ __align__(16) float sB[200 * 20];     // [k within chunk][sub]  (16 KB)
    const int tid = threadIdx.x;
    const int t = blockIdx.x * 256 + tid;
    const bool active = (t < T_DATA);

    for (int phase = 0; phase < 2; ++phase) {
        const float* A = phase ? Si : Se;
        const float* B = phase ? Ci : Ce;
        const int K = phase ? I_NO : E_NO;
        const int nchunk = K / 200;

        float acc[20];
#pragma unroll
        for (int s = 0; s < 20; ++s) acc[s] = 0.f;

        for (int chn = 0; chn < nchunk; ++chn) {
            const int k0 = chn * 200;
            __syncthreads();
            for (int i = tid; i < 200 * 20; i += 256) {
                int su = i / 200, kk = i % 200;
                sB[kk * 20 + su] = B[su * K + k0 + kk];
            }
            __syncthreads();
            if (active) {
                const float4* a4 = reinterpret_cast<const float4*>(A + (long)t * K + k0);
#pragma unroll 2
                for (int k4 = 0; k4 < 50; ++k4) {
                    float4 a = a4[k4];
#pragma unroll
                    for (int m = 0; m < 4; ++m) {
                        float av = (m == 0) ? a.x : (m == 1) ? a.y : (m == 2) ? a.z : a.w;
                        const float* brow = &sB[(k4 * 4 + m) * 20];
#pragma unroll
                        for (int sg = 0; sg < 5; ++sg) {
                            float4 b = *reinterpret_cast<const float4*>(brow + sg * 4);
                            acc[sg * 4 + 0] += av * b.x;
                            acc[sg * 4 + 1] += av * b.y;
                            acc[sg * 4 + 2] += av * b.z;
                            acc[sg * 4 + 3] += av * b.w;
                        }
                    }
                }
            }
        }
        if (active) {
#pragma unroll
            for (int s = 0; s < 20; ++s)
                g_S[(long)(2 * s + phase) * S_PITCH + 199 + t] = acc[s];
        }
        __syncthreads();
    }
}

// ---------------- fused conv (causal, 200 taps, 2 in-ch) + leaky + 2x16 MLP + root partial ----
// grid: (ceil(T/512), SUB_NO), block 256.  thread: hg=tid>>6 (4 h), tg=tid&63 (8 t)
__global__ __launch_bounds__(256, 3) void conv_mlp_kernel(const float* __restrict__ ff_w,
                                                          const float* __restrict__ ff_b,
                                                          const float* __restrict__ ff2_w,
                                                          const float* __restrict__ ff2_b,
                                                          const float* __restrict__ root_w) {
    __shared__ __align__(16) float sm[9104];
    // conv phase: sK = sm[0..6400)  [c][h][d],   sS = sm[6400..7824)  [2][712]
    // mlp  phase: sX = sm[0..8448)  [16][528],   weights after
    float* sK = sm;
    float* sS = sm + 6400;
    const int s = blockIdx.y;
    const int t0 = blockIdx.x * CONV_TT;
    const int tid = threadIdx.x;

    // straight vectorized copies (g_kern2 pre-transposed)
    {
        const float4* gk4 = reinterpret_cast<const float4*>(g_kern2 + (long)s * 6400);
        float4* sK4 = reinterpret_cast<float4*>(sK);
        for (int i = tid; i < 1600; i += 256) sK4[i] = gk4[i];
        // S window: x in [0, 712)  (global t = t0 + x - 199)
        for (int i = tid; i < 2 * 178; i += 256) {
            int c = i / 178, x4 = i % 178;
            reinterpret_cast<float4*>(sS + c * 712)[x4] =
                *reinterpret_cast<const float4*>(g_S + (long)(2 * s + c) * S_PITCH + t0 + x4 * 4);
        }
    }
    __syncthreads();

    const int hg = tid >> 6;       // 4 h-groups (x4 h each)
    const int tg = tid & 63;       // 64 t-groups (x8 t each)
    const int tb = tg * 8;

    float acc[4][8];
#pragma unroll
    for (int h = 0; h < 4; ++h)
#pragma unroll
        for (int j = 0; j < 8; ++j) acc[h][j] = 0.f;

    for (int c = 0; c < 2; ++c) {
        const float* kc = sK + c * (H_NO * T_NO) + (hg * 4) * T_NO;
        const float* sc = sS + c * 712;
#pragma unroll 2
        for (int d = 0; d < T_NO; d += 4) {
            float kk[4][4];
#pragma unroll
            for (int h = 0; h < 4; ++h) {
                float4 kv = *reinterpret_cast<const float4*>(kc + h * T_NO + d);
                kk[h][0] = kv.x; kk[h][1] = kv.y; kk[h][2] = kv.z; kk[h][3] = kv.w;
            }
            const int x0 = tb + 196 - d;           // sS index of S[t0+tb - d - 3]
            float w[12];
            float4 wa = *reinterpret_cast<const float4*>(sc + x0);
            float4 wb = *reinterpret_cast<const float4*>(sc + x0 + 4);
            float4 wc = *reinterpret_cast<const float4*>(sc + x0 + 8);
            w[0] = wa.x; w[1] = wa.y; w[2] = wa.z; w[3] = wa.w;
            w[4] = wb.x; w[5] = wb.y; w[6] = wb.z; w[7] = wb.w;
            w[8] = wc.x; w[9] = wc.y; w[10] = wc.z; w[11] = wc.w;
#pragma unroll
            for (int h = 0; h < 4; ++h)
#pragma unroll
                for (int m = 0; m < 4; ++m)
#pragma unroll
                    for (int j = 0; j < 8; ++j)
                        acc[h][j] += kk[h][m] * w[j + 3 - m];
        }
    }
    __syncthreads();   // done with sK/sS; reuse for sX/weights

    float* sX  = sm;            // [16][528] = 8448
    float* sW1 = sm + 8448;     // 256
    float* sW2 = sm + 8704;     // 256
    float* sb1 = sm + 8960;     // 16
    float* sb2 = sm + 8976;     // 16
    float* sr  = sm + 8992;     // 16
#pragma unroll
    for (int h = 0; h < 4; ++h) {
        float4 v0, v1;
        v0.x = acc[h][0] > 0.f ? acc[h][0] : 0.01f * acc[h][0];
        v0.y = acc[h][1] > 0.f ? acc[h][1] : 0.01f * acc[h][1];
        v0.z = acc[h][2] > 0.f ? acc[h][2] : 0.01f * acc[h][2];
        v0.w = acc[h][3] > 0.f ? acc[h][3] : 0.01f * acc[h][3];
        v1.x = acc[h][4] > 0.f ? acc[h][4] : 0.01f * acc[h][4];
        v1.y = acc[h][5] > 0.f ? acc[h][5] : 0.01f * acc[h][5];
        v1.z = acc[h][6] > 0.f ? acc[h][6] : 0.01f * acc[h][6];
        v1.w = acc[h][7] > 0.f ? acc[h][7] : 0.01f * acc[h][7];
        int hglob = hg * 4 + h;
        *reinterpret_cast<float4*>(&sX[hglob * 528 + tb])     = v0;
        *reinterpret_cast<float4*>(&sX[hglob * 528 + tb + 4]) = v1;
    }
    if (tid < 256) {
        sW1[tid] = ff_w[s * 256 + tid];
        sW2[tid] = ff2_w[s * 256 + tid];
    }
    if (tid < 16) {
        sb1[tid] = ff_b[s * 16 + tid];
        sb2[tid] = ff2_b[s * 16 + tid];
        sr[tid]  = root_w[s * 16 + tid];
    }
    __syncthreads();

#pragma unroll
    for (int tt = 0; tt < 2; ++tt) {
        int tl = tid + tt * 256;
        int t = t0 + tl;
        if (t < T_DATA) {
            float x[16];
#pragma unroll
            for (int i = 0; i < 16; ++i) x[i] = sX[i * 528 + tl];
            float h1[16];
#pragma unroll
            for (int o = 0; o < 16; ++o) {
                float4 w0 = *reinterpret_cast<const float4*>(&sW1[o * 16]);
                float4 w1 = *reinterpret_cast<const float4*>(&sW1[o * 16 + 4]);
                float4 w2 = *reinterpret_cast<const float4*>(&sW1[o * 16 + 8]);
                float4 w3 = *reinterpret_cast<const float4*>(&sW1[o * 16 + 12]);
                float a = sb1[o];
                a += w0.x * x[0] + w0.y * x[1] + w0.z * x[2] + w0.w * x[3];
                a += w1.x * x[4] + w1.y * x[5] + w1.z * x[6] + w1.w * x[7];
                a += w2.x * x[8] + w2.y * x[9] + w2.z * x[10] + w2.w * x[11];
                a += w3.x * x[12] + w3.y * x[13] + w3.z * x[14] + w3.w * x[15];
                h1[o] = a > 0.f ? a : 0.01f * a;
            }
            float part = 0.f;
#pragma unroll
            for (int o = 0; o < 16; ++o) {
                float4 w0 = *reinterpret_cast<const float4*>(&sW2[o * 16]);
                float4 w1 = *reinterpret_cast<const float4*>(&sW2[o * 16 + 4]);
                float4 w2 = *reinterpret_cast<const float4*>(&sW2[o * 16 + 8]);
                float4 w3 = *reinterpret_cast<const float4*>(&sW2[o * 16 + 12]);
                float a = sb2[o];
                a += w0.x * h1[0] + w0.y * h1[1] + w0.z * h1[2] + w0.w * h1[3];
                a += w1.x * h1[4] + w1.y * h1[5] + w1.z * h1[6] + w1.w * h1[7];
                a += w2.x * h1[8] + w2.y * h1[9] + w2.z * h1[10] + w2.w * h1[11];
                a += w3.x * h1[12] + w3.y * h1[13] + w3.z * h1[14] + w3.w * h1[15];
                float h2 = a > 0.f ? a : 0.01f * a;
                part += sr[o] * h2;
            }
            g_partial[(long)s * T_DATA + t] = part;
        }
    }
}

// ---------------- reduce over subunits + bias ----------------
__global__ void reduce_kernel(const float* __restrict__ root_b,
                              const float* __restrict__ V_o,
                              float* __restrict__ out) {
    int t = blockIdx.x * blockDim.x + threadIdx.x;
    if (t >= T_DATA) return;
    float acc = root_b[0] + V_o[0];
#pragma unroll
    for (int s = 0; s < SUB_NO; ++s) acc += g_partial[(long)s * T_DATA + t];
    out[t] = acc;
}

// ---------------- launch ----------------
extern "C" void kernel_launch(void* const* d_in, const int* in_sizes, int n_in,
                              void* d_out, int out_size) {
    const float* S_e    = (const float*)d_in[0];
    const float* S_i    = (const float*)d_in[1];
    const float* C_e    = (const float*)d_in[2];
    const float* C_i    = (const float*)d_in[3];
    const float* W_conv = (const float*)d_in[4];
    const float* ff_w   = (const float*)d_in[5];
    const float* ff_b   = (const float*)d_in[6];
    const float* ff2_w  = (const float*)d_in[7];
    const float* ff2_b  = (const float*)d_in[8];
    const float* root_w = (const float*)d_in[9];
    const float* root_b = (const float*)d_in[10];
    const float* V_o    = (const float*)d_in[11];
    float* out = (float*)d_out;

    // zero only the pad + tail of g_S
    const int per_ch = 199 + (S_PITCH - (199 + T_DATA));
    zero_pad_kernel<<<(2 * SUB_NO * per_ch + 255) / 256, 256>>>();

    // temporal kernels (transposed scratch); flipped copy goes to output if it fits
    float* kern_out = (out_size >= T_DATA + SUB_NO * H_NO * 2 * T_NO) ? (out + T_DATA) : nullptr;
    kern_basis_kernel<<<(SUB_NO * H_NO * 2 * T_NO + 255) / 256, 256>>>(W_conv, kern_out);

    // synapse grouping GEMMs -> interleaved channel-major g_S
    gemm1_kernel<<<(T_DATA + 255) / 256, 256>>>(S_e, S_i, C_e, C_i);

    // fused conv + MLP + root partials
    dim3 grid((T_DATA + CONV_TT - 1) / CONV_TT, SUB_NO);
    conv_mlp_kernel<<<grid, 256>>>(ff_w, ff_b, ff2_w, ff2_b, root_w);

    // final reduction -> V
    reduce_kernel<<<(T_DATA + 255) / 256, 256>>>(root_b, V_o, out);
}

// round 4
// speedup vs baseline: 1.3531x; 1.0720x over previous
#include <cuda_runtime.h>
#include <math.h>

#define T_DATA   50000
#define E_NO     1000
#define I_NO     200
#define SUB_NO   20
#define H_NO     16
#define T_NO     200
#define COS_NO   20

#define S_PITCH  50432            // 199 pad + 50000 + tail overhang, float4 aligned
#define CONV_TT  512              // time tile for conv kernel
#define PI_F     3.14159265358979323846f
#define HALF_PI_F 1.57079632679489662f

typedef unsigned long long ull;

// ---------------- f32x2 helpers (Blackwell packed fp32) ----------------
__device__ __forceinline__ ull pack2(float lo, float hi) {
    ull r; asm("mov.b64 %0, {%1, %2};" : "=l"(r) : "f"(lo), "f"(hi)); return r;
}
__device__ __forceinline__ void fma2(ull& d, ull a, ull b) {
    asm("fma.rn.f32x2 %0, %1, %2, %0;" : "+l"(d) : "l"(a), "l"(b));
}
__device__ __forceinline__ float2 unpack2(ull v) {
    float2 f; asm("mov.b64 {%0, %1}, %2;" : "=f"(f.x), "=f"(f.y) : "l"(v)); return f;
}

// ---------------- device scratch (no allocations allowed) ----------------
__device__ float g_S[2 * SUB_NO * S_PITCH];          // [40][S_PITCH], ch-major, pad 199 zeros
__device__ float g_kern2[SUB_NO * 2 * H_NO * T_NO];  // [s][c][h/2][d][h%2] pair-interleaved
__device__ float g_partial[SUB_NO * T_DATA];         // per-subunit root partials

// ---------------- zero only pad + tail of g_S ----------------
__global__ void zero_pad_kernel() {
    int i = blockIdx.x * blockDim.x + threadIdx.x;
    const int per_ch = 199 + (S_PITCH - (199 + T_DATA));   // 432
    if (i >= 2 * SUB_NO * per_ch) return;
    int ch = i / per_ch;
    int r = i % per_ch;
    int x = (r < 199) ? r : (199 + T_DATA) + (r - 199);
    g_S[(long)ch * S_PITCH + x] = 0.f;
}

// ---------------- basis * W_conv -> g_kern2 (+ flipped copy to output) ----------------
__global__ void kern_basis_kernel(const float* __restrict__ W_conv,
                                  float* __restrict__ out_kern /* may be null */) {
    int n = blockIdx.x * blockDim.x + threadIdx.x;
    if (n >= SUB_NO * H_NO * 2 * T_NO) return;
    int o = n / (2 * T_NO);          // o = s*16 + h
    int r = n % (2 * T_NO);
    int c = r / T_NO;
    int t = r % T_NO;
    int s = o / H_NO;
    int h = o % H_NO;
    float raw = 5.0f * logf((float)t + 1.0f);
    float acc = 0.f;
#pragma unroll
    for (int b = 0; b < COS_NO; ++b) {
        float phi = HALF_PI_F * (float)b;
        float dlt = raw - phi;
        if (raw >= phi - PI_F && raw <= phi + PI_F) {
            float bas = 0.5f * cosf(dlt) + 0.5f;
            acc += W_conv[(o * 2 + c) * COS_NO + b] * bas;
        }
    }
    // pair-interleaved layout: [s][c][h2=h/2 (8)][d (200)][p=h&1 (2)]
    g_kern2[(((s * 2 + c) * 8 + (h >> 1)) * T_NO + t) * 2 + (h & 1)] = acc;
    if (out_kern) out_kern[o * 2 * T_NO + c * T_NO + (T_NO - 1 - t)] = acc;  // flipped (returned)
}

// ---------------- GEMM1: Sg = S @ C^T, f32x2 over subunit pairs ----------------
// sB layout: [sp(10)][k(200)][p(2)] -> LDS.128 at (sp,k even) = pairs for k and k+1
__global__ __launch_bounds__(256) void gemm1_kernel(const float* __restrict__ Se,
                                                    const float* __restrict__ Si,
                                                    const float* __restrict__ Ce,
                                                    const float* __restrict__ Ci) {
    __shared__ __align__(16) float sB[10 * 200 * 2];     // 16 KB
    const int tid = threadIdx.x;
    const int t = blockIdx.x * 256 + tid;
    const bool active = (t < T_DATA);

    for (int phase = 0; phase < 2; ++phase) {
        const float* A = phase ? Si : Se;
        const float* B = phase ? Ci : Ce;
        const int K = phase ? I_NO : E_NO;
        const int nchunk = K / 200;

        ull acc2[10];
#pragma unroll
        for (int sp = 0; sp < 10; ++sp) acc2[sp] = 0ull;

        for (int chn = 0; chn < nchunk; ++chn) {
            const int k0 = chn * 200;
            __syncthreads();
            for (int i = tid; i < 200 * 20; i += 256) {
                int su = i / 200, kk = i % 200;
                sB[((su >> 1) * 200 + kk) * 2 + (su & 1)] = B[su * K + k0 + kk];
            }
            __syncthreads();
            if (active) {
                const float4* a4 = reinterpret_cast<const float4*>(A + (long)t * K + k0);
#pragma unroll 2
                for (int k4 = 0; k4 < 50; ++k4) {
                    float4 a = a4[k4];
                    ull ap[4];
                    ap[0] = pack2(a.x, a.x); ap[1] = pack2(a.y, a.y);
                    ap[2] = pack2(a.z, a.z); ap[3] = pack2(a.w, a.w);
#pragma unroll
                    for (int kp = 0; kp < 2; ++kp) {           // two k-pairs within k4
                        const int kb = k4 * 4 + kp * 2;
#pragma unroll
                        for (int sp = 0; sp < 10; sp += 2) {
                            // two sub-pairs x (k, k+1)
                            ulonglong2 b0 = *reinterpret_cast<const ulonglong2*>(&sB[(sp * 200 + kb) * 2]);
                            ulonglong2 b1 = *reinterpret_cast<const ulonglong2*>(&sB[((sp + 1) * 200 + kb) * 2]);
                            fma2(acc2[sp],     ap[kp * 2],     b0.x);
                            fma2(acc2[sp],     ap[kp * 2 + 1], b0.y);
                            fma2(acc2[sp + 1], ap[kp * 2],     b1.x);
                            fma2(acc2[sp + 1], ap[kp * 2 + 1], b1.y);
                        }
                    }
                }
            }
        }
        if (active) {
#pragma unroll
            for (int sp = 0; sp < 10; ++sp) {
                float2 v = unpack2(acc2[sp]);
                g_S[(long)(2 * (2 * sp) + phase) * S_PITCH + 199 + t]     = v.x;
                g_S[(long)(2 * (2 * sp + 1) + phase) * S_PITCH + 199 + t] = v.y;
            }
        }
        __syncthreads();
    }
}

// ---------------- fused conv (f32x2 over h-pairs) + leaky + 2x16 MLP + root partial ----
// grid: (ceil(T/512), SUB_NO), block 256.  thread: hg=tid>>6 (4 h), tg=tid&63 (8 t)
__global__ __launch_bounds__(256, 2) void conv_mlp_kernel(const float* __restrict__ ff_w,
                                                          const float* __restrict__ ff_b,
                                                          const float* __restrict__ ff2_w,
                                                          const float* __restrict__ ff2_b,
                                                          const float* __restrict__ root_w) {
    __shared__ __align__(16) float sm[9104];
    // conv phase: sK = sm[0..6400)  [c][h2(8)][d(200)][p(2)],  sS = sm[6400..7824) [2][712]
    // mlp  phase: sX = sm[0..8448)  [16][528],  weights after
    float* sK = sm;
    float* sS = sm + 6400;
    const int s = blockIdx.y;
    const int t0 = blockIdx.x * CONV_TT;
    const int tid = threadIdx.x;

    {
        const float4* gk4 = reinterpret_cast<const float4*>(g_kern2 + (long)s * 6400);
        float4* sK4 = reinterpret_cast<float4*>(sK);
        for (int i = tid; i < 1600; i += 256) sK4[i] = gk4[i];
        for (int i = tid; i < 2 * 178; i += 256) {
            int c = i / 178, x4 = i % 178;
            reinterpret_cast<float4*>(sS + c * 712)[x4] =
                *reinterpret_cast<const float4*>(g_S + (long)(2 * s + c) * S_PITCH + t0 + x4 * 4);
        }
    }
    __syncthreads();

    const int hg = tid >> 6;       // 4 h-groups (4 h each = 2 h-pairs)
    const int tg = tid & 63;       // 64 t-groups (8 t each)
    const int tb = tg * 8;

    ull acc2[2][8];                 // [h-pair within hg][time j], packed (h even, h odd)
#pragma unroll
    for (int h2 = 0; h2 < 2; ++h2)
#pragma unroll
        for (int j = 0; j < 8; ++j) acc2[h2][j] = 0ull;

    for (int c = 0; c < 2; ++c) {
        // kernel base for this hg: pairs h2g = hg*2 + h2
        const float* kc = sK + (c * 8 + hg * 2) * (T_NO * 2);
        const float* sc = sS + c * 712;
#pragma unroll 2
        for (int d = 0; d < T_NO; d += 4) {
            // kernel pairs: aligned LDS.128 = {(d,p0),(d,p1),(d+1,p0),(d+1,p1)} = pairs m=0,1
            ull kk2[2][4];
#pragma unroll
            for (int h2 = 0; h2 < 2; ++h2) {
                ulonglong2 kva = *reinterpret_cast<const ulonglong2*>(kc + h2 * (T_NO * 2) + d * 2);
                ulonglong2 kvb = *reinterpret_cast<const ulonglong2*>(kc + h2 * (T_NO * 2) + d * 2 + 4);
                kk2[h2][0] = kva.x; kk2[h2][1] = kva.y;
                kk2[h2][2] = kvb.x; kk2[h2][3] = kvb.y;
            }
            const int x0 = tb + 196 - d;           // sS index of S[t0+tb - d - 3]
            float w[12];
            float4 wa = *reinterpret_cast<const float4*>(sc + x0);
            float4 wb = *reinterpret_cast<const float4*>(sc + x0 + 4);
            float4 wc = *reinterpret_cast<const float4*>(sc + x0 + 8);
            w[0] = wa.x; w[1] = wa.y; w[2] = wa.z; w[3] = wa.w;
            w[4] = wb.x; w[5] = wb.y; w[6] = wb.z; w[7] = wb.w;
            w[8] = wc.x; w[9] = wc.y; w[10] = wc.z; w[11] = wc.w;
            ull wp[11];
#pragma unroll
            for (int x = 0; x < 11; ++x) wp[x] = pack2(w[x], w[x]);
            // acc2[h2][j] += kk2[h2][m] * w[j+3-m]   (elementwise over the h-pair)
#pragma unroll
            for (int h2 = 0; h2 < 2; ++h2)
#pragma unroll
                for (int m = 0; m < 4; ++m)
#pragma unroll
                    for (int j = 0; j < 8; ++j)
                        fma2(acc2[h2][j], kk2[h2][m], wp[j + 3 - m]);
        }
    }
    __syncthreads();   // done with sK/sS; reuse for sX/weights

    float* sX  = sm;            // [16][528] = 8448
    float* sW1 = sm + 8448;     // 256
    float* sW2 = sm + 8704;     // 256
    float* sb1 = sm + 8960;     // 16
    float* sb2 = sm + 8976;     // 16
    float* sr  = sm + 8992;     // 16
#pragma unroll
    for (int h2 = 0; h2 < 2; ++h2) {
        float a0[8], a1[8];
#pragma unroll
        for (int j = 0; j < 8; ++j) {
            float2 v = unpack2(acc2[h2][j]);
            a0[j] = v.x > 0.f ? v.x : 0.01f * v.x;
            a1[j] = v.y > 0.f ? v.y : 0.01f * v.y;
        }
        int hb = hg * 4 + h2 * 2;
        *reinterpret_cast<float4*>(&sX[hb * 528 + tb])           = make_float4(a0[0], a0[1], a0[2], a0[3]);
        *reinterpret_cast<float4*>(&sX[hb * 528 + tb + 4])       = make_float4(a0[4], a0[5], a0[6], a0[7]);
        *reinterpret_cast<float4*>(&sX[(hb + 1) * 528 + tb])     = make_float4(a1[0], a1[1], a1[2], a1[3]);
        *reinterpret_cast<float4*>(&sX[(hb + 1) * 528 + tb + 4]) = make_float4(a1[4], a1[5], a1[6], a1[7]);
    }
    if (tid < 256) {
        sW1[tid] = ff_w[s * 256 + tid];
        sW2[tid] = ff2_w[s * 256 + tid];
    }
    if (tid < 16) {
        sb1[tid] = ff_b[s * 16 + tid];
        sb2[tid] = ff2_b[s * 16 + tid];
        sr[tid]  = root_w[s * 16 + tid];
    }
    __syncthreads();

#pragma unroll
    for (int tt = 0; tt < 2; ++tt) {
        int tl = tid + tt * 256;
        int t = t0 + tl;
        if (t < T_DATA) {
            float x[16];
#pragma unroll
            for (int i = 0; i < 16; ++i) x[i] = sX[i * 528 + tl];
            float h1[16];
#pragma unroll
            for (int o = 0; o < 16; ++o) {
                float4 w0 = *reinterpret_cast<const float4*>(&sW1[o * 16]);
                float4 w1 = *reinterpret_cast<const float4*>(&sW1[o * 16 + 4]);
                float4 w2 = *reinterpret_cast<const float4*>(&sW1[o * 16 + 8]);
                float4 w3 = *reinterpret_cast<const float4*>(&sW1[o * 16 + 12]);
                float a = sb1[o];
                a += w0.x * x[0] + w0.y * x[1] + w0.z * x[2] + w0.w * x[3];
                a += w1.x * x[4] + w1.y * x[5] + w1.z * x[6] + w1.w * x[7];
                a += w2.x * x[8] + w2.y * x[9] + w2.z * x[10] + w2.w * x[11];
                a += w3.x * x[12] + w3.y * x[13] + w3.z * x[14] + w3.w * x[15];
                h1[o] = a > 0.f ? a : 0.01f * a;
            }
            float part = 0.f;
#pragma unroll
            for (int o = 0; o < 16; ++o) {
                float4 w0 = *reinterpret_cast<const float4*>(&sW2[o * 16]);
                float4 w1 = *reinterpret_cast<const float4*>(&sW2[o * 16 + 4]);
                float4 w2 = *reinterpret_cast<const float4*>(&sW2[o * 16 + 8]);
                float4 w3 = *reinterpret_cast<const float4*>(&sW2[o * 16 + 12]);
                float a = sb2[o];
                a += w0.x * h1[0] + w0.y * h1[1] + w0.z * h1[2] + w0.w * h1[3];
                a += w1.x * h1[4] + w1.y * h1[5] + w1.z * h1[6] + w1.w * h1[7];
                a += w2.x * h1[8] + w2.y * h1[9] + w2.z * h1[10] + w2.w * h1[11];
                a += w3.x * h1[12] + w3.y * h1[13] + w3.z * h1[14] + w3.w * h1[15];
                float h2v = a > 0.f ? a : 0.01f * a;
                part += sr[o] * h2v;
            }
            g_partial[(long)s * T_DATA + t] = part;
        }
    }
}

// ---------------- reduce over subunits + bias ----------------
__global__ void reduce_kernel(const float* __restrict__ root_b,
                              const float* __restrict__ V_o,
                              float* __restrict__ out) {
    int t = blockIdx.x * blockDim.x + threadIdx.x;
    if (t >= T_DATA) return;
    float acc = root_b[0] + V_o[0];
#pragma unroll
    for (int s = 0; s < SUB_NO; ++s) acc += g_partial[(long)s * T_DATA + t];
    out[t] = acc;
}

// ---------------- launch ----------------
extern "C" void kernel_launch(void* const* d_in, const int* in_sizes, int n_in,
                              void* d_out, int out_size) {
    const float* S_e    = (const float*)d_in[0];
    const float* S_i    = (const float*)d_in[1];
    const float* C_e    = (const float*)d_in[2];
    const float* C_i    = (const float*)d_in[3];
    const float* W_conv = (const float*)d_in[4];
    const float* ff_w   = (const float*)d_in[5];
    const float* ff_b   = (const float*)d_in[6];
    const float* ff2_w  = (const float*)d_in[7];
    const float* ff2_b  = (const float*)d_in[8];
    const float* root_w = (const float*)d_in[9];
    const float* root_b = (const float*)d_in[10];
    const float* V_o    = (const float*)d_in[11];
    float* out = (float*)d_out;

    const int per_ch = 199 + (S_PITCH - (199 + T_DATA));
    zero_pad_kernel<<<(2 * SUB_NO * per_ch + 255) / 256, 256>>>();

    float* kern_out = (out_size >= T_DATA + SUB_NO * H_NO * 2 * T_NO) ? (out + T_DATA) : nullptr;
    kern_basis_kernel<<<(SUB_NO * H_NO * 2 * T_NO + 255) / 256, 256>>>(W_conv, kern_out);

    gemm1_kernel<<<(T_DATA + 255) / 256, 256>>>(S_e, S_i, C_e, C_i);

    dim3 grid((T_DATA + CONV_TT - 1) / CONV_TT, SUB_NO);
    conv_mlp_kernel<<<grid, 256>>>(ff_w, ff_b, ff2_w, ff2_b, root_w);

    reduce_kernel<<<(T_DATA + 255) / 256, 256>>>(root_b, V_o, out);
}